// round 5
// baseline (speedup 1.0000x reference)
#include <cuda_runtime.h>
#include <cuda_bf16.h>

// InfoNCE loss (fused gather + dot + log-softmax + mean), single kernel.
//   inputs: embeddings f32 [100000,128], targets i32 [16384],
//           contexts i32 [16384], negatives i32 [16384,20]
//   output: scalar f32 loss
//
// One warp per batch element, grid-stride over elements (persistent single
// wave: 592 blocks = 148 SMs x 4 blocks). Lane l holds float4 [4l,4l+4) of
// each row (coalesced 512B warp gathers). All 21 logits reduced with a
// multi-value transpose butterfly (23 shuffles; zero-pairs skipped), leaving
// lane l with logit bitrev5(l). Next element's indices are prefetched during
// the current element's gathers. Final reduction: per-block partials to a
// __device__ scratch array, last block sums and writes the scalar.

#define BATCH   16384
#define NUM_NEG 20
#define NLOGITS (NUM_NEG + 1)
#define INV_T   (1.0f / 0.07f)
#define FULL    0xFFFFFFFFu
#define GRID    592
#define WPB     8
#define NWARPS  (GRID * WPB)   // 4736

__device__ float    g_part[GRID];
__device__ unsigned g_cnt = 0;

__device__ __forceinline__ float process_element(
    const float4* __restrict__ e4,
    int tgt_i, int ctx_i, int4 q0, int4 q1, int4 q2, int4 q3, int4 q4,
    int lane)
{
    // target row: lane l -> elements [4l, 4l+4)
    const float4 t = e4[(size_t)tgt_i * 32 + lane];

    int idx[NLOGITS];
    idx[0] = ctx_i;
    idx[1] = q0.x;  idx[2]  = q0.y;  idx[3]  = q0.z;  idx[4]  = q0.w;
    idx[5] = q1.x;  idx[6]  = q1.y;  idx[7]  = q1.z;  idx[8]  = q1.w;
    idx[9] = q2.x;  idx[10] = q2.y;  idx[11] = q2.z;  idx[12] = q2.w;
    idx[13] = q3.x; idx[14] = q3.y;  idx[15] = q3.z;  idx[16] = q3.w;
    idx[17] = q4.x; idx[18] = q4.y;  idx[19] = q4.z;  idx[20] = q4.w;

    // 21 gathered per-lane partial dots (unrolled -> loads batch up)
    float val[32];
    #pragma unroll
    for (int k = 0; k < NLOGITS; k++) {
        const float4 v = e4[(size_t)idx[k] * 32 + lane];
        val[k] = fmaf(t.x, v.x, fmaf(t.y, v.y, fmaf(t.z, v.z, t.w * v.w)));
    }
    #pragma unroll
    for (int k = NLOGITS; k < 32; k++) val[k] = 0.0f;

    // Multi-value transpose butterfly; pairs whose operands are all-zero are
    // replaced by val[i]=0 (8 shuffles saved). After 5 stages lane l holds
    // the warp-summed logit bitrev5(l).
    int live = NLOGITS;
    #pragma unroll
    for (int m = 16; m >= 1; m >>= 1) {
        const int np = (live + 1) >> 1;
        #pragma unroll
        for (int i = 0; i < m; i++) {
            if (i < np) {
                const float a = val[2 * i];
                const float c = val[2 * i + 1];
                const bool hi = (lane & m) != 0;
                const float keep = hi ? c : a;
                const float sent = hi ? a : c;
                val[i] = keep + __shfl_xor_sync(FULL, sent, m);
            } else {
                val[i] = 0.0f;
            }
        }
        live = np;
    }

    const float x = val[0] * INV_T;                 // logit bitrev5(lane)
    const int logit_id = (int)(__brev((unsigned)lane) >> 27);
    const bool valid = logit_id < NLOGITS;

    float xm = valid ? x : -__int_as_float(0x7f800000);
    #pragma unroll
    for (int o = 16; o >= 1; o >>= 1)
        xm = fmaxf(xm, __shfl_xor_sync(FULL, xm, o));

    float e = valid ? __expf(x - xm) : 0.0f;
    #pragma unroll
    for (int o = 16; o >= 1; o >>= 1)
        e += __shfl_xor_sync(FULL, e, o);

    const float pos = __shfl_sync(FULL, x, 0);      // lane 0 holds logit 0
    return xm + __logf(e) - pos;
}

__global__ __launch_bounds__(256, 4) void infonce_kernel(
    const float* __restrict__ emb,
    const int* __restrict__ targets,
    const int* __restrict__ contexts,
    const int* __restrict__ negatives,
    float* __restrict__ out)
{
    const int lane = threadIdx.x & 31;
    const int warp_in_blk = threadIdx.x >> 5;
    const int gw = blockIdx.x * WPB + warp_in_blk;   // 0..4735

    const float4* __restrict__ e4 = (const float4*)emb;
    const int4*   __restrict__ n4 = (const int4*)negatives;

    float acc = 0.0f;

    // prefetch first element's indices (gw < NWARPS <= BATCH always valid)
    int b = gw;
    int  p_tgt = targets[b];
    int  p_ctx = contexts[b];
    int4 p0 = n4[b * 5 + 0], p1 = n4[b * 5 + 1], p2 = n4[b * 5 + 2],
         p3 = n4[b * 5 + 3], p4 = n4[b * 5 + 4];

    while (true) {
        const int  c_tgt = p_tgt, c_ctx = p_ctx;
        const int4 c0 = p0, c1 = p1, c2 = p2, c3 = p3, c4 = p4;

        const int bn = b + NWARPS;
        const bool has_next = bn < BATCH;
        if (has_next) {   // prefetch next element's indices (overlaps gathers)
            p_tgt = targets[bn];
            p_ctx = contexts[bn];
            p0 = n4[bn * 5 + 0]; p1 = n4[bn * 5 + 1]; p2 = n4[bn * 5 + 2];
            p3 = n4[bn * 5 + 3]; p4 = n4[bn * 5 + 4];
        }

        acc += process_element(e4, c_tgt, c_ctx, c0, c1, c2, c3, c4, lane);

        if (!has_next) break;
        b = bn;
    }

    // block reduce: 8 warps -> smem
    __shared__ float part[WPB];
    __shared__ bool  is_last;
    if (lane == 0) part[warp_in_blk] = acc;
    __syncthreads();
    if (threadIdx.x == 0) {
        float tot = 0.0f;
        #pragma unroll
        for (int w = 0; w < WPB; w++) tot += part[w];
        g_part[blockIdx.x] = tot;
        __threadfence();
        const unsigned old = atomicAdd(&g_cnt, 1u);
        is_last = (old == GRID - 1);
    }
    __syncthreads();

    // last block: warp 0 reduces the 592 partials and writes the scalar
    if (is_last && warp_in_blk == 0) {
        float s = 0.0f;
        for (int i = lane; i < GRID; i += 32) s += g_part[i];
        #pragma unroll
        for (int o = 16; o >= 1; o >>= 1)
            s += __shfl_xor_sync(FULL, s, o);
        if (lane == 0) {
            out[0] = s * (1.0f / (float)BATCH);
            g_cnt = 0;   // reset for next graph replay
        }
    }
}

extern "C" void kernel_launch(void* const* d_in, const int* in_sizes, int n_in,
                              void* d_out, int out_size) {
    const float* emb = (const float*)d_in[0];
    const int*   tgt = (const int*)d_in[1];
    const int*   ctx = (const int*)d_in[2];
    const int*   neg = (const int*)d_in[3];
    float* out = (float*)d_out;

    infonce_kernel<<<GRID, WPB * 32>>>(emb, tgt, ctx, neg, out);
}

// round 6
// speedup vs baseline: 1.0702x; 1.0702x over previous
#include <cuda_runtime.h>
#include <cuda_bf16.h>

// InfoNCE loss (fused gather + dot + log-softmax + mean), single kernel.
//   inputs: embeddings f32 [100000,128], targets i32 [16384],
//           contexts i32 [16384], negatives i32 [16384,20]
//   output: scalar f32 loss
//
// One warp per batch element (2048 blocks x 8 warps). Lane l holds float4
// [4l,4l+4) of each row (coalesced 512B warp gathers). All 21 logits reduced
// with a multi-value transpose butterfly (23 shuffles; zero-pairs skipped),
// leaving lane l with logit bitrev5(l). Final reduction is fused: per-block
// partials to a __device__ array; the last block (atomic counter) reduces
// 2048 partials with all 8 warps and writes the scalar. No separate
// zero-kernel launch.

#define BATCH   16384
#define NUM_NEG 20
#define NLOGITS (NUM_NEG + 1)
#define INV_T   (1.0f / 0.07f)
#define FULL    0xFFFFFFFFu
#define WPB     8
#define GRID    (BATCH / WPB)   // 2048

__device__ float    g_part[GRID];
__device__ unsigned g_cnt = 0;

__global__ __launch_bounds__(256) void infonce_kernel(
    const float* __restrict__ emb,
    const int* __restrict__ targets,
    const int* __restrict__ contexts,
    const int* __restrict__ negatives,
    float* __restrict__ out)
{
    const int lane = threadIdx.x & 31;
    const int warp_in_blk = threadIdx.x >> 5;
    const int b = (blockIdx.x << 3) + warp_in_blk;

    const float4* __restrict__ e4 = (const float4*)emb;

    // target row: lane l -> elements [4l, 4l+4)
    const float4 t = e4[(size_t)targets[b] * 32 + lane];

    // indices: context + 20 negatives (5x int4 broadcast loads)
    int idx[NLOGITS];
    idx[0] = contexts[b];
    const int4* __restrict__ n4 = (const int4*)(negatives + b * NUM_NEG);
    #pragma unroll
    for (int j = 0; j < 5; j++) {
        const int4 q = n4[j];
        idx[4 * j + 1] = q.x;
        idx[4 * j + 2] = q.y;
        idx[4 * j + 3] = q.z;
        idx[4 * j + 4] = q.w;
    }

    // 21 gathered per-lane partial dots (unrolled -> loads batch up)
    float val[32];
    #pragma unroll
    for (int k = 0; k < NLOGITS; k++) {
        const float4 v = e4[(size_t)idx[k] * 32 + lane];
        val[k] = fmaf(t.x, v.x, fmaf(t.y, v.y, fmaf(t.z, v.z, t.w * v.w)));
    }
    #pragma unroll
    for (int k = NLOGITS; k < 32; k++) val[k] = 0.0f;

    // Multi-value transpose butterfly; pairs whose operands are all zero are
    // skipped (23 shuffles total). After 5 stages lane l holds the
    // warp-summed logit with index bitrev5(l).
    int live = NLOGITS;
    #pragma unroll
    for (int m = 16; m >= 1; m >>= 1) {
        const int np = (live + 1) >> 1;
        #pragma unroll
        for (int i = 0; i < m; i++) {
            if (i < np) {
                const float a = val[2 * i];
                const float c = val[2 * i + 1];
                const bool hi = (lane & m) != 0;
                const float keep = hi ? c : a;
                const float sent = hi ? a : c;
                val[i] = keep + __shfl_xor_sync(FULL, sent, m);
            } else {
                val[i] = 0.0f;
            }
        }
        live = np;
    }

    const float x = val[0] * INV_T;                 // logit bitrev5(lane)
    const int logit_id = (int)(__brev((unsigned)lane) >> 27);
    const bool valid = logit_id < NLOGITS;

    // warp max over valid lanes
    float xm = valid ? x : -__int_as_float(0x7f800000);
    #pragma unroll
    for (int o = 16; o >= 1; o >>= 1)
        xm = fmaxf(xm, __shfl_xor_sync(FULL, xm, o));

    // warp sum of exp
    float e = valid ? __expf(x - xm) : 0.0f;
    #pragma unroll
    for (int o = 16; o >= 1; o >>= 1)
        e += __shfl_xor_sync(FULL, e, o);

    const float pos = __shfl_sync(FULL, x, 0);      // lane 0 holds logit 0
    const float loss = xm + __logf(e) - pos;

    // block reduce: 8 warps -> smem -> device partial
    __shared__ float part[WPB];
    __shared__ bool  is_last;
    if (lane == 0) part[warp_in_blk] = loss;
    __syncthreads();
    if (threadIdx.x == 0) {
        float tot = 0.0f;
        #pragma unroll
        for (int w = 0; w < WPB; w++) tot += part[w];
        g_part[blockIdx.x] = tot;
        __threadfence();
        is_last = (atomicAdd(&g_cnt, 1u) == GRID - 1);
    }
    __syncthreads();

    // last block: all 8 warps reduce the 2048 partials, write the scalar
    if (is_last) {
        float s = 0.0f;
        #pragma unroll
        for (int j = 0; j < GRID / 256; j++)      // 8 per thread
            s += g_part[j * 256 + threadIdx.x];
        #pragma unroll
        for (int o = 16; o >= 1; o >>= 1)
            s += __shfl_xor_sync(FULL, s, o);
        if (lane == 0) part[warp_in_blk] = s;
        __syncthreads();
        if (threadIdx.x == 0) {
            float tot = 0.0f;
            #pragma unroll
            for (int w = 0; w < WPB; w++) tot += part[w];
            out[0] = tot * (1.0f / (float)BATCH);
            g_cnt = 0;   // reset for next graph replay
        }
    }
}

extern "C" void kernel_launch(void* const* d_in, const int* in_sizes, int n_in,
                              void* d_out, int out_size) {
    const float* emb = (const float*)d_in[0];
    const int*   tgt = (const int*)d_in[1];
    const int*   ctx = (const int*)d_in[2];
    const int*   neg = (const int*)d_in[3];
    float* out = (float*)d_out;

    infonce_kernel<<<GRID, WPB * 32>>>(emb, tgt, ctx, neg, out);
}

// round 7
// speedup vs baseline: 1.1267x; 1.0528x over previous
#include <cuda_runtime.h>
#include <cuda_bf16.h>

// InfoNCE loss (fused gather + dot + log-softmax + mean), single kernel.
//   inputs: embeddings f32 [100000,128], targets i32 [16384],
//           contexts i32 [16384], negatives i32 [16384,20]
//   output: scalar f32 loss
//
// One warp per batch element (2048 blocks x 8 warps). Lane l holds float4
// [4l,4l+4) of each row (coalesced 512B warp gathers). All 21 logits reduced
// with a multi-value transpose butterfly (23 shuffles), leaving lane l with
// logit bitrev5(l). Cross-block reduction is FENCE-FREE: each block
// atomicAdds its partial into g_accum, then (dependent on the returned old
// value, so the L2 RMW has completed) increments g_cnt; the last block reads
// g_accum atomically and writes the scalar. No __threadfence -> no CCTL.IVALL
// L1 flush (which regressed R6 by 3.4us).

#define BATCH   16384
#define NUM_NEG 20
#define NLOGITS (NUM_NEG + 1)
#define INV_T   (1.0f / 0.07f)
#define FULL    0xFFFFFFFFu
#define WPB     8
#define GRID    (BATCH / WPB)   // 2048

__device__ float    g_accum = 0.0f;
__device__ unsigned g_cnt = 0;

__global__ __launch_bounds__(256) void infonce_kernel(
    const float* __restrict__ emb,
    const int* __restrict__ targets,
    const int* __restrict__ contexts,
    const int* __restrict__ negatives,
    float* __restrict__ out)
{
    const int lane = threadIdx.x & 31;
    const int warp_in_blk = threadIdx.x >> 5;
    const int b = (blockIdx.x << 3) + warp_in_blk;

    const float4* __restrict__ e4 = (const float4*)emb;

    // target row: lane l -> elements [4l, 4l+4)
    const float4 t = e4[(size_t)targets[b] * 32 + lane];

    // indices: context + 20 negatives (5x int4 broadcast loads; rows are
    // 80B = 5*16B so int4 alignment holds for every b)
    int idx[NLOGITS];
    idx[0] = contexts[b];
    const int4* __restrict__ n4 = (const int4*)(negatives + b * NUM_NEG);
    #pragma unroll
    for (int j = 0; j < 5; j++) {
        const int4 q = n4[j];
        idx[4 * j + 1] = q.x;
        idx[4 * j + 2] = q.y;
        idx[4 * j + 3] = q.z;
        idx[4 * j + 4] = q.w;
    }

    // 21 gathered per-lane partial dots (unrolled -> loads batch up)
    float val[32];
    #pragma unroll
    for (int k = 0; k < NLOGITS; k++) {
        const float4 v = e4[(size_t)idx[k] * 32 + lane];
        val[k] = fmaf(t.x, v.x, fmaf(t.y, v.y, fmaf(t.z, v.z, t.w * v.w)));
    }
    #pragma unroll
    for (int k = NLOGITS; k < 32; k++) val[k] = 0.0f;

    // Multi-value transpose butterfly; all-zero pairs skipped (23 shuffles).
    // After 5 stages lane l holds the warp-summed logit bitrev5(l).
    int live = NLOGITS;
    #pragma unroll
    for (int m = 16; m >= 1; m >>= 1) {
        const int np = (live + 1) >> 1;
        #pragma unroll
        for (int i = 0; i < m; i++) {
            if (i < np) {
                const float a = val[2 * i];
                const float c = val[2 * i + 1];
                const bool hi = (lane & m) != 0;
                const float keep = hi ? c : a;
                const float sent = hi ? a : c;
                val[i] = keep + __shfl_xor_sync(FULL, sent, m);
            } else {
                val[i] = 0.0f;
            }
        }
        live = np;
    }

    const float x = val[0] * INV_T;                 // logit bitrev5(lane)
    const int logit_id = (int)(__brev((unsigned)lane) >> 27);
    const bool valid = logit_id < NLOGITS;

    // warp max over valid lanes
    float xm = valid ? x : -__int_as_float(0x7f800000);
    #pragma unroll
    for (int o = 16; o >= 1; o >>= 1)
        xm = fmaxf(xm, __shfl_xor_sync(FULL, xm, o));

    // warp sum of exp
    float e = valid ? __expf(x - xm) : 0.0f;
    #pragma unroll
    for (int o = 16; o >= 1; o >>= 1)
        e += __shfl_xor_sync(FULL, e, o);

    const float pos = __shfl_sync(FULL, x, 0);      // lane 0 holds logit 0
    const float loss = xm + __logf(e) - pos;

    // block reduce: 8 warps -> smem; tid0 -> fence-free global accumulation
    __shared__ float part[WPB];
    __shared__ bool  is_last;
    if (lane == 0) part[warp_in_blk] = loss;
    __syncthreads();
    if (threadIdx.x == 0) {
        float tot = 0.0f;
        #pragma unroll
        for (int w = 0; w < WPB; w++) tot += part[w];
        // value-add first; its returned old value feeds (via a dependency the
        // compiler cannot break) the count-add, so the L2 RMW ordering holds.
        const float old = atomicAdd(&g_accum, tot);
        unsigned dep = __float_as_uint(old) & 0u;   // 0, but data-dependent
        is_last = (atomicAdd(&g_cnt, 1u + dep) == GRID - 1);
    }
    __syncthreads();

    if (is_last && threadIdx.x == 0) {
        const float total = atomicAdd(&g_accum, 0.0f);  // coherent L2 read
        out[0] = total * (1.0f / (float)BATCH);
        g_accum = 0.0f;   // reset for next graph replay
        g_cnt = 0;        // (kernel boundary orders these vs next replay)
    }
}

extern "C" void kernel_launch(void* const* d_in, const int* in_sizes, int n_in,
                              void* d_out, int out_size) {
    const float* emb = (const float*)d_in[0];
    const int*   tgt = (const int*)d_in[1];
    const int*   ctx = (const int*)d_in[2];
    const int*   neg = (const int*)d_in[3];
    float* out = (float*)d_out;

    infonce_kernel<<<GRID, WPB * 32>>>(emb, tgt, ctx, neg, out);
}

// round 8
// speedup vs baseline: 1.1636x; 1.0327x over previous
#include <cuda_runtime.h>
#include <cuda_bf16.h>

// InfoNCE loss (fused gather + dot + log-softmax + mean).
//   inputs: embeddings f32 [100000,128], targets i32 [16384],
//           contexts i32 [16384], negatives i32 [16384,20]
//   output: scalar f32 loss
//
// R4 body (best measured): one warp per batch element; lane l holds float4
// [4l,4l+4) of each row (coalesced 512B warp gathers). All 21 logits reduced
// with a multi-value transpose butterfly (23 shuffles, zero-pairs skipped),
// leaving lane l with logit bitrev5(l); one exp per lane. Per-block partial
// goes straight to out[0] via atomicAdd with UNUSED result -> REDG
// (fire-and-forget, no block lingering). out is zeroed by a cudaMemsetAsync
// graph memset node (cheaper than a 1-thread zero kernel; R6/R7 showed any
// in-kernel completion protocol costs more than the zeroing node).

#define BATCH   16384
#define NUM_NEG 20
#define NLOGITS (NUM_NEG + 1)
#define INV_T   (1.0f / 0.07f)
#define FULL    0xFFFFFFFFu
#define WPB     8
#define GRID    (BATCH / WPB)   // 2048

__global__ __launch_bounds__(256) void infonce_kernel(
    const float* __restrict__ emb,
    const int* __restrict__ targets,
    const int* __restrict__ contexts,
    const int* __restrict__ negatives,
    float* __restrict__ out)
{
    const int lane = threadIdx.x & 31;
    const int warp_in_blk = threadIdx.x >> 5;
    const int b = (blockIdx.x << 3) + warp_in_blk;

    const float4* __restrict__ e4 = (const float4*)emb;

    // target row: lane l -> elements [4l, 4l+4)
    const float4 t = e4[(size_t)targets[b] * 32 + lane];

    // indices: context + 20 negatives (5x int4 broadcast loads; rows are
    // 80B = 5*16B so int4 alignment holds for every b)
    int idx[NLOGITS];
    idx[0] = contexts[b];
    const int4* __restrict__ n4 = (const int4*)(negatives + b * NUM_NEG);
    #pragma unroll
    for (int j = 0; j < 5; j++) {
        const int4 q = n4[j];
        idx[4 * j + 1] = q.x;
        idx[4 * j + 2] = q.y;
        idx[4 * j + 3] = q.z;
        idx[4 * j + 4] = q.w;
    }

    // 21 gathered per-lane partial dots (unrolled -> loads batch up)
    float val[32];
    #pragma unroll
    for (int k = 0; k < NLOGITS; k++) {
        const float4 v = e4[(size_t)idx[k] * 32 + lane];
        val[k] = fmaf(t.x, v.x, fmaf(t.y, v.y, fmaf(t.z, v.z, t.w * v.w)));
    }
    #pragma unroll
    for (int k = NLOGITS; k < 32; k++) val[k] = 0.0f;

    // Multi-value transpose butterfly; all-zero pairs skipped (23 shuffles).
    // After 5 stages lane l holds the warp-summed logit bitrev5(l).
    int live = NLOGITS;
    #pragma unroll
    for (int m = 16; m >= 1; m >>= 1) {
        const int np = (live + 1) >> 1;
        #pragma unroll
        for (int i = 0; i < m; i++) {
            if (i < np) {
                const float a = val[2 * i];
                const float c = val[2 * i + 1];
                const bool hi = (lane & m) != 0;
                const float keep = hi ? c : a;
                const float sent = hi ? a : c;
                val[i] = keep + __shfl_xor_sync(FULL, sent, m);
            } else {
                val[i] = 0.0f;
            }
        }
        live = np;
    }

    const float x = val[0] * INV_T;                 // logit bitrev5(lane)
    const int logit_id = (int)(__brev((unsigned)lane) >> 27);
    const bool valid = logit_id < NLOGITS;

    // warp max over valid lanes
    float xm = valid ? x : -__int_as_float(0x7f800000);
    #pragma unroll
    for (int o = 16; o >= 1; o >>= 1)
        xm = fmaxf(xm, __shfl_xor_sync(FULL, xm, o));

    // warp sum of exp
    float e = valid ? __expf(x - xm) : 0.0f;
    #pragma unroll
    for (int o = 16; o >= 1; o >>= 1)
        e += __shfl_xor_sync(FULL, e, o);

    const float pos = __shfl_sync(FULL, x, 0);      // lane 0 holds logit 0
    const float loss = (xm + __logf(e) - pos) * (1.0f / (float)BATCH);

    // block reduce: 8 warps -> smem -> one fire-and-forget REDG per block
    __shared__ float part[WPB];
    if (lane == 0) part[warp_in_blk] = loss;
    __syncthreads();
    if (threadIdx.x == 0) {
        float tot = 0.0f;
        #pragma unroll
        for (int w = 0; w < WPB; w++) tot += part[w];
        atomicAdd(out, tot);   // result unused -> REDG, no wait
    }
}

extern "C" void kernel_launch(void* const* d_in, const int* in_sizes, int n_in,
                              void* d_out, int out_size) {
    const float* emb = (const float*)d_in[0];
    const int*   tgt = (const int*)d_in[1];
    const int*   ctx = (const int*)d_in[2];
    const int*   neg = (const int*)d_in[3];
    float* out = (float*)d_out;

    // zero the scalar accumulator via a graph memset node (async, capturable)
    cudaMemsetAsync(out, 0, sizeof(float), 0);

    infonce_kernel<<<GRID, WPB * 32>>>(emb, tgt, ctx, neg, out);
}